// round 12
// baseline (speedup 1.0000x reference)
#include <cuda_runtime.h>
#include <math.h>

#define Bn 8
#define Hn 192
#define Wn 192
#define NTOT (Bn*Hn*Wn)
#define NCH 6                     // 192 rows = 6 x u32 words
#define BIGD (1 << 20)

typedef unsigned long long ull;

__device__ unsigned g_mask[2][Bn][NCH][Wn];   // fg bit per (row chunk, col)
__device__ int      g_hasany[2][Bn][NCH];
__device__ float    g_part[Bn*Hn];
__device__ unsigned g_count = 0;

// ---------------------------------------------------------------------------
// Kernel A: per-column fg bitmasks. Block = (tensor, b, 32-row chunk),
// blockDim (192,2): each thread builds 16 bits; halves composed via shared.
// ---------------------------------------------------------------------------
__global__ void mask_kernel(const float* __restrict__ pred,
                            const float* __restrict__ tgt) {
    const int blk = blockIdx.x;               // t*48 + b*6 + chunk
    const int t = blk / (Bn * NCH);
    const int r = blk % (Bn * NCH);
    const int b = r / NCH;
    const int chunk = r % NCH;
    const float* src = t ? tgt : pred;
    const int w = threadIdx.x;
    const int y = threadIdx.y;                // 0 = low 16 rows, 1 = high 16
    const int h0 = chunk * 32 + y * 16;

    unsigned part = 0;
    #pragma unroll
    for (int i = 0; i < 16; ++i) {
        float v = src[(b * Hn + h0 + i) * Wn + w];
        bool fg = t ? (v > 0.5f) : (v > 0.0f);   // sigmoid(v)>0.5 <=> v>0
        part |= (unsigned)fg << i;
    }

    __shared__ unsigned sm[Wn];
    if (y == 0) sm[w] = part;
    int any = __syncthreads_or(part != 0u);
    if (y == 1) g_mask[t][b][chunk][w] = sm[w] | (part << 16);
    if (w == 0 && y == 0) g_hasany[t][b][chunk] = any;
}

// ---------------------------------------------------------------------------
// Distance from row h (word c, bit position `bit`, uniform per block) to the
// nearest set bit of the 192-bit mask (m0 lowest). Word selection via uniform
// ternaries -> SEL, no dynamically indexed register arrays (no local memory).
// ---------------------------------------------------------------------------
__device__ __forceinline__ int nearest_set3(ull m0, ull m1, ull m2,
                                            int c, int bit) {
    ull a   = (c == 0) ? m0 : ((c == 1) ? m1 : m2);
    ull dn1 = (c == 0) ? m1 : ((c == 1) ? m2 : 0ULL);
    ull dn2 = (c == 0) ? m2 : 0ULL;
    ull up1 = (c == 2) ? m1 : ((c == 1) ? m0 : 0ULL);
    ull up2 = (c == 2) ? m0 : 0ULL;

    int down, up;
    ull x = a & (~0ULL << bit);                 // bits >= h within word c
    if (x)        down = __ffsll(x) - 1 - bit;
    else if (dn1) down = 64  + __ffsll(dn1) - 1 - bit;
    else if (dn2) down = 128 + __ffsll(dn2) - 1 - bit;
    else          down = BIGD;

    x = a << (63 - bit);                        // bits <= h shifted to MSB
    if (x)        up = __clzll(x);
    else if (up1) up = bit + 1  + __clzll(up1);
    else if (up2) up = bit + 65 + __clzll(up2);
    else          up = BIGD;

    return min(up, down);
}

// ---------------------------------------------------------------------------
// Kernel B: EDT identity -> one column scan + one row-DT per tensor.
// Row DT: branchless speculative window d=1..4 (16 independent LDS, exact --
// extra candidates only lower toward the true min), then a rarely-taken
// residual loop for d>=5 with the exact break d^2 >= bmax.
// ---------------------------------------------------------------------------
__global__ void rowpass_kernel(const float* __restrict__ pred,
                               const float* __restrict__ tgt,
                               float* __restrict__ out) {
    const int b = blockIdx.x / Hn;
    const int h = blockIdx.x % Hn;
    const int p = threadIdx.x;
    const int c = h >> 6, bit = h & 63;         // uniform per block

    __shared__ float ssq[4][3 * Wn];            // [class][pad | data | pad]
    __shared__ float wsum[6];
    __shared__ int   s_last;

    // prefetch everything global early; latency hides under scan + DT
    const int idx = (b * Hn + h) * Wn + p;
    const float x  = pred[idx];
    const float tv = tgt[idx];
    int hp = 0, ht = 0;
    #pragma unroll
    for (int j = 0; j < NCH; ++j) {
        hp |= g_hasany[0][b][j];
        ht |= g_hasany[1][b][j];
    }

    // pad borders (sentinel larger than any real candidate)
    #pragma unroll
    for (int k = 0; k < 4; ++k) {
        ssq[k][p]        = 1.0e12f;
        ssq[k][p + 2*Wn] = 1.0e12f;
    }

    // load 192-bit column masks (6 coalesced u32 loads per tensor)
    ull mp0, mp1, mp2, mt0, mt1, mt2;
    {
        const unsigned* gp = &g_mask[0][b][0][p];
        const unsigned* gt = &g_mask[1][b][0][p];
        mp0 = (ull)gp[0*Wn] | ((ull)gp[1*Wn] << 32);
        mp1 = (ull)gp[2*Wn] | ((ull)gp[3*Wn] << 32);
        mp2 = (ull)gp[4*Wn] | ((ull)gp[5*Wn] << 32);
        mt0 = (ull)gt[0*Wn] | ((ull)gt[1*Wn] << 32);
        mt1 = (ull)gt[2*Wn] | ((ull)gt[3*Wn] << 32);
        mt2 = (ull)gt[4*Wn] | ((ull)gt[5*Wn] << 32);
    }
    ull wp = (c == 0) ? mp0 : ((c == 1) ? mp1 : mp2);
    ull wt = (c == 0) ? mt0 : ((c == 1) ? mt1 : mt2);
    const bool fgP = (wp >> bit) & 1ULL;
    const bool fgT = (wt >> bit) & 1ULL;

    // column distance to nearest OPPOSITE-class pixel
    int dP = nearest_set3(fgP ? ~mp0 : mp0, fgP ? ~mp1 : mp1,
                          fgP ? ~mp2 : mp2, c, bit);
    int dT = nearest_set3(fgT ? ~mt0 : mt0, fgT ? ~mt1 : mt1,
                          fgT ? ~mt2 : mt2, c, bit);
    float dsqP = (dP >= BIGD) ? 1.0e12f : (float)(dP * dP);
    float dsqT = (dT >= BIGD) ? 1.0e12f : (float)(dT * dT);
    ssq[0][Wn + p] = fgP ? dsqP : 0.0f;         // pred fg-EDT col dist^2
    ssq[1][Wn + p] = fgP ? 0.0f : dsqP;         // pred bg-EDT col dist^2
    ssq[2][Wn + p] = fgT ? dsqT : 0.0f;
    ssq[3][Wn + p] = fgT ? 0.0f : dsqT;
    __syncthreads();

    const float* aP = (fgP ? ssq[0] : ssq[1]) + Wn + p;
    const float* aT = (fgT ? ssq[2] : ssq[3]) + Wn + p;
    float bp = aP[0];
    float bt = aT[0];

    // branchless speculative window d = 1..4: 16 independent LDS, fmin tree
    #pragma unroll
    for (int d = 1; d <= 4; ++d) {
        float dd = (float)(d * d);
        bp = fminf(bp, dd + fminf(aP[-d], aP[d]));
        bt = fminf(bt, dd + fminf(aT[-d], aT[d]));
    }
    float bmax = fmaxf(bp, bt);

    // residual (rare): exact break d^2 >= bmax
    if (bmax > 25.0f) {
        for (int d = 5; d < Wn; ++d) {
            float dd = (float)(d * d);
            if (dd >= bmax) break;
            bp = fminf(bp, dd + fminf(aP[-d], aP[d]));
            bt = fminf(bt, dd + fminf(aT[-d], aT[d]));
            bmax = fmaxf(bp, bt);
        }
    }

    // other-class D is exactly 0 -> field = sqrt(D_own)
    float pd = sqrtf(bp) * (float)hp;
    float td = sqrtf(bt) * (float)ht;

    float sg = 1.0f / (1.0f + __expf(-x));
    float e  = sg - tv;
    e = e * e;

    float num = pd * pd + td * td;
    float den = pd + td;
    den = den * den;
    float v = e * (num / den);

    // deterministic block reduction
    #pragma unroll
    for (int o = 16; o > 0; o >>= 1)
        v += __shfl_down_sync(0xffffffffu, v, o);
    if ((p & 31) == 0) wsum[p >> 5] = v;
    __syncthreads();
    if (p == 0) {
        float s = 0.0f;
        #pragma unroll
        for (int i = 0; i < 6; ++i) s += wsum[i];
        g_part[blockIdx.x] = s;
        __threadfence();
        unsigned ticket = atomicAdd(&g_count, 1u);
        s_last = (ticket == (unsigned)(gridDim.x - 1));
    }
    __syncthreads();

    // last finishing block: deterministic fixed-order fp64 final reduction.
    if (s_last) {
        __shared__ double dsm[Wn];
        double s = 0.0;
        for (int i = p; i < Bn * Hn; i += Wn)
            s += (double)g_part[i];
        dsm[p] = s;
        __syncthreads();
        #pragma unroll
        for (int o = 96; o >= 3; o >>= 1) {     // 192->96->...->3
            if (p < o) dsm[p] += dsm[p + o];
            __syncthreads();
        }
        if (p == 0) {
            double tot = dsm[0] + dsm[1] + dsm[2];
            out[0] = (float)(tot / (double)NTOT);
            g_count = 0;
        }
    }
}

extern "C" void kernel_launch(void* const* d_in, const int* in_sizes, int n_in,
                              void* d_out, int out_size) {
    const float* pred = (const float*)d_in[0];
    const float* tgt  = (const float*)d_in[1];
    float* out = (float*)d_out;
    (void)in_sizes; (void)n_in; (void)out_size;

    dim3 mb(Wn, 2);
    mask_kernel<<<2 * Bn * NCH, mb>>>(pred, tgt);
    rowpass_kernel<<<Bn * Hn, Wn>>>(pred, tgt, out);
}

// round 13
// speedup vs baseline: 1.0172x; 1.0172x over previous
#include <cuda_runtime.h>
#include <math.h>

#define Bn 8
#define Hn 192
#define Wn 192
#define NTOT (Bn*Hn*Wn)
#define NCH 6                     // 192 rows = 6 x u32 words
#define BIGD (1 << 20)

typedef unsigned long long ull;

__device__ unsigned g_mask[2][Bn][NCH][Wn];   // fg bit per (row chunk, col)
__device__ int      g_hasany[2][Bn][NCH];
__device__ float    g_part[Bn*Hn];
__device__ unsigned g_count = 0;

// ---------------------------------------------------------------------------
// Kernel A: per-column fg bitmasks. Block = (tensor, b, 32-row chunk),
// blockDim (192,2): each thread builds 16 bits; halves composed via shared.
// ---------------------------------------------------------------------------
__global__ void mask_kernel(const float* __restrict__ pred,
                            const float* __restrict__ tgt) {
    const int blk = blockIdx.x;               // t*48 + b*6 + chunk
    const int t = blk / (Bn * NCH);
    const int r = blk % (Bn * NCH);
    const int b = r / NCH;
    const int chunk = r % NCH;
    const float* src = t ? tgt : pred;
    const int w = threadIdx.x;
    const int y = threadIdx.y;                // 0 = low 16 rows, 1 = high 16
    const int h0 = chunk * 32 + y * 16;

    unsigned part = 0;
    #pragma unroll
    for (int i = 0; i < 16; ++i) {
        float v = src[(b * Hn + h0 + i) * Wn + w];
        bool fg = t ? (v > 0.5f) : (v > 0.0f);   // sigmoid(v)>0.5 <=> v>0
        part |= (unsigned)fg << i;
    }

    __shared__ unsigned sm[Wn];
    if (y == 0) sm[w] = part;
    int any = __syncthreads_or(part != 0u);
    if (y == 1) g_mask[t][b][chunk][w] = sm[w] | (part << 16);
    if (w == 0 && y == 0) g_hasany[t][b][chunk] = any;
}

// ---------------------------------------------------------------------------
// Distance from row h (word c, bit position `bit`, uniform per block) to the
// nearest set bit of the 192-bit mask (m0 lowest). Word selection via uniform
// ternaries -> SEL, no dynamically indexed register arrays (no local memory).
// ---------------------------------------------------------------------------
__device__ __forceinline__ int nearest_set3(ull m0, ull m1, ull m2,
                                            int c, int bit) {
    ull a   = (c == 0) ? m0 : ((c == 1) ? m1 : m2);
    ull dn1 = (c == 0) ? m1 : ((c == 1) ? m2 : 0ULL);
    ull dn2 = (c == 0) ? m2 : 0ULL;
    ull up1 = (c == 2) ? m1 : ((c == 1) ? m0 : 0ULL);
    ull up2 = (c == 2) ? m0 : 0ULL;

    int down, up;
    ull x = a & (~0ULL << bit);                 // bits >= h within word c
    if (x)        down = __ffsll(x) - 1 - bit;
    else if (dn1) down = 64  + __ffsll(dn1) - 1 - bit;
    else if (dn2) down = 128 + __ffsll(dn2) - 1 - bit;
    else          down = BIGD;

    x = a << (63 - bit);                        // bits <= h shifted to MSB
    if (x)        up = __clzll(x);
    else if (up1) up = bit + 1  + __clzll(up1);
    else if (up2) up = bit + 65 + __clzll(up2);
    else          up = BIGD;

    return min(up, down);
}

// ---------------------------------------------------------------------------
// Kernel B: EDT identity -> one column scan + one row-DT per tensor.
// Cross-block completion protocol uses scoped release/acquire atomics + L2
// (stcg/ldcg) instead of __threadfence: fence.gpu emits CCTL.IVALL on sm_103a
// (full L1D flush per block) which was poisoning co-resident blocks' L1.
// ---------------------------------------------------------------------------
__global__ void rowpass_kernel(const float* __restrict__ pred,
                               const float* __restrict__ tgt,
                               float* __restrict__ out) {
    const int b = blockIdx.x / Hn;
    const int h = blockIdx.x % Hn;
    const int p = threadIdx.x;
    const int c = h >> 6, bit = h & 63;         // uniform per block

    __shared__ float ssq[4][3 * Wn];            // [class][pad | data | pad]
    __shared__ float wsum[6];
    __shared__ int   s_last;

    // prefetch everything global early; latency hides under scan + DT
    const int idx = (b * Hn + h) * Wn + p;
    const float x  = pred[idx];
    const float tv = tgt[idx];
    int hp = 0, ht = 0;
    #pragma unroll
    for (int j = 0; j < NCH; ++j) {
        hp |= g_hasany[0][b][j];
        ht |= g_hasany[1][b][j];
    }

    // pad borders (sentinel larger than any real candidate)
    #pragma unroll
    for (int k = 0; k < 4; ++k) {
        ssq[k][p]        = 1.0e12f;
        ssq[k][p + 2*Wn] = 1.0e12f;
    }

    // load 192-bit column masks (6 coalesced u32 loads per tensor)
    ull mp0, mp1, mp2, mt0, mt1, mt2;
    {
        const unsigned* gp = &g_mask[0][b][0][p];
        const unsigned* gt = &g_mask[1][b][0][p];
        mp0 = (ull)gp[0*Wn] | ((ull)gp[1*Wn] << 32);
        mp1 = (ull)gp[2*Wn] | ((ull)gp[3*Wn] << 32);
        mp2 = (ull)gp[4*Wn] | ((ull)gp[5*Wn] << 32);
        mt0 = (ull)gt[0*Wn] | ((ull)gt[1*Wn] << 32);
        mt1 = (ull)gt[2*Wn] | ((ull)gt[3*Wn] << 32);
        mt2 = (ull)gt[4*Wn] | ((ull)gt[5*Wn] << 32);
    }
    ull wp = (c == 0) ? mp0 : ((c == 1) ? mp1 : mp2);
    ull wt = (c == 0) ? mt0 : ((c == 1) ? mt1 : mt2);
    const bool fgP = (wp >> bit) & 1ULL;
    const bool fgT = (wt >> bit) & 1ULL;

    // column distance to nearest OPPOSITE-class pixel
    int dP = nearest_set3(fgP ? ~mp0 : mp0, fgP ? ~mp1 : mp1,
                          fgP ? ~mp2 : mp2, c, bit);
    int dT = nearest_set3(fgT ? ~mt0 : mt0, fgT ? ~mt1 : mt1,
                          fgT ? ~mt2 : mt2, c, bit);
    float dsqP = (dP >= BIGD) ? 1.0e12f : (float)(dP * dP);
    float dsqT = (dT >= BIGD) ? 1.0e12f : (float)(dT * dT);
    ssq[0][Wn + p] = fgP ? dsqP : 0.0f;         // pred fg-EDT col dist^2
    ssq[1][Wn + p] = fgP ? 0.0f : dsqP;         // pred bg-EDT col dist^2
    ssq[2][Wn + p] = fgT ? dsqT : 0.0f;
    ssq[3][Wn + p] = fgT ? 0.0f : dsqT;
    __syncthreads();

    const float* aP = (fgP ? ssq[0] : ssq[1]) + Wn + p;
    const float* aT = (fgT ? ssq[2] : ssq[3]) + Wn + p;
    float bp = aP[0];
    float bt = aT[0];

    // branchless speculative window d = 1..4: independent LDS, fmin tree
    #pragma unroll
    for (int d = 1; d <= 4; ++d) {
        float dd = (float)(d * d);
        bp = fminf(bp, dd + fminf(aP[-d], aP[d]));
        bt = fminf(bt, dd + fminf(aT[-d], aT[d]));
    }
    float bmax = fmaxf(bp, bt);

    // residual (rare): exact break d^2 >= bmax
    if (bmax > 25.0f) {
        for (int d = 5; d < Wn; ++d) {
            float dd = (float)(d * d);
            if (dd >= bmax) break;
            bp = fminf(bp, dd + fminf(aP[-d], aP[d]));
            bt = fminf(bt, dd + fminf(aT[-d], aT[d]));
            bmax = fmaxf(bp, bt);
        }
    }

    // other-class D is exactly 0 -> field = sqrt(D_own)
    float pd = sqrtf(bp) * (float)hp;
    float td = sqrtf(bt) * (float)ht;

    float sg = 1.0f / (1.0f + __expf(-x));
    float e  = sg - tv;
    e = e * e;

    float num = pd * pd + td * td;
    float den = pd + td;
    den = den * den;
    float v = e * (num / den);

    // deterministic block reduction
    #pragma unroll
    for (int o = 16; o > 0; o >>= 1)
        v += __shfl_down_sync(0xffffffffu, v, o);
    if ((p & 31) == 0) wsum[p >> 5] = v;
    __syncthreads();
    if (p == 0) {
        float s = 0.0f;
        #pragma unroll
        for (int i = 0; i < 6; ++i) s += wsum[i];
        __stcg(&g_part[blockIdx.x], s);         // straight to L2
        unsigned ticket;
        // release orders the partial store; acquire (in last block) pairs it.
        // No fence.gpu -> no CCTL.IVALL L1 flush.
        asm volatile("atom.acq_rel.gpu.global.add.u32 %0, [%1], %2;"
                     : "=r"(ticket)
                     : "l"(&g_count), "r"(1u)
                     : "memory");
        s_last = (ticket == (unsigned)(gridDim.x - 1));
    }
    __syncthreads();   // broadcasts thread0's acquire ordering CTA-wide

    // last finishing block: deterministic fixed-order fp64 final reduction.
    if (s_last) {
        __shared__ double dsm[Wn];
        double s = 0.0;
        for (int i = p; i < Bn * Hn; i += Wn)
            s += (double)__ldcg(&g_part[i]);    // read from L2, never stale L1
        dsm[p] = s;
        __syncthreads();
        #pragma unroll
        for (int o = 96; o >= 3; o >>= 1) {     // 192->96->...->3
            if (p < o) dsm[p] += dsm[p + o];
            __syncthreads();
        }
        if (p == 0) {
            double tot = dsm[0] + dsm[1] + dsm[2];
            out[0] = (float)(tot / (double)NTOT);
            g_count = 0;
        }
    }
}

extern "C" void kernel_launch(void* const* d_in, const int* in_sizes, int n_in,
                              void* d_out, int out_size) {
    const float* pred = (const float*)d_in[0];
    const float* tgt  = (const float*)d_in[1];
    float* out = (float*)d_out;
    (void)in_sizes; (void)n_in; (void)out_size;

    dim3 mb(Wn, 2);
    mask_kernel<<<2 * Bn * NCH, mb>>>(pred, tgt);
    rowpass_kernel<<<Bn * Hn, Wn>>>(pred, tgt, out);
}